// round 15
// baseline (speedup 1.0000x reference)
#include <cuda_runtime.h>

#define SAMPLES 32
#define THREADS 256

#define SIN_STR 324    // staged input per-sample stride: 16 rows x 20 cols (+4 pad)
#define C1STR   808    // conv1-out per-sample stride: [y][8 xx][12 ch] rows of 100 (+8 pad)
#define O2STR   33     // conv2-out transposed: [192 k][33]

enum {
    OFF_C1   = 0,                          // 32 * 808 = 25856
    OFF_R2   = 32 * C1STR,                 // 25856: input stage (32*324=10368), later out2t
    OFF_HID  = OFF_R2 + 192 * O2STR,       // 32192 (+1024 = 33216 <= 36224, inside stage)
    OFF_W1T  = OFF_R2 + 32 * SIN_STR,      // 36224: w1 [25 tap][12 ch]
    OFF_B1T  = OFF_W1T + 304,              // 36528: b1 pairs [6 j][8 xx][8 y][2]
    OFF_W2T  = OFF_B1T + 768,              // 37296: w2 [25 tap][12 o][8 j]
    OFF_H2B  = OFF_W2T + 2400,             // 39696: [12][16]
    OFF_W3T  = OFF_H2B + 192,              // 39888: w3 [30 h][192 k]
    OFF_H3B  = OFF_W3T + 5760,             // 45648
    OFF_OUTW = OFF_H3B + 32,               // 45680: [30][10]
    OFF_OUTB = OFF_OUTW + 304,             // 45984
    OFF_NEG  = OFF_OUTB + 16,              // 46000: 20 floats of -1 (shared pad row)
    SMEM_FLOATS = OFF_NEG + 20             // 46020 floats = 184080 B
};

typedef unsigned long long ull;

__device__ __forceinline__ ull pk2(float a, float b) {
    ull r; asm("mov.b64 %0, {%1, %2};" : "=l"(r) : "f"(a), "f"(b)); return r;
}
__device__ __forceinline__ void fma2(ull& d, ull a, ull b) {
    asm("fma.rn.f32x2 %0, %1, %2, %0;" : "+l"(d) : "l"(a), "l"(b));
}
__device__ __forceinline__ void unpk2(ull v, float& lo, float& hi) {
    asm("mov.b64 {%0, %1}, %2;" : "=f"(lo), "=f"(hi) : "l"(v));
}

__global__ void __launch_bounds__(THREADS, 1)
modernnet_fused_kernel(const float* __restrict__ x,
                       const float* __restrict__ w1,   // [12,1,5,5]
                       const float* __restrict__ b1,   // [12,8,8]
                       const float* __restrict__ w2,   // [12,8,5,5]
                       const float* __restrict__ b2,   // [12,4,4]
                       const float* __restrict__ w3,   // [192,30]
                       const float* __restrict__ b3,   // [30]
                       const float* __restrict__ wo,   // [30,10]
                       const float* __restrict__ bo,   // [10]
                       float* __restrict__ out,        // [B,10]
                       int nsamp)
{
    extern __shared__ float sm[];
    const int t = threadIdx.x;
    const long base_s = (long)blockIdx.x * SAMPLES;

    // ---------------- Phase A: stage input (with -1 halo) + weights ----------
    for (int i = t; i < SAMPLES * 320; i += THREADS) {
        int s = i / 320, rem = i - s * 320;
        int r = rem / 20, c20 = rem - r * 20;
        int cc = c20 - 2;                       // halo cols -2..17
        long gs = base_s + s;
        float v = -1.0f;
        if ((unsigned)cc < 16u && gs < nsamp) v = x[gs * 256 + r * 16 + cc];
        sm[OFF_R2 + s * SIN_STR + r * 20 + c20] = v;
    }
    // w1t[k*12 + c] = w1[c*25 + k]
    for (int i = t; i < 300; i += THREADS) {
        int c = i / 25, k = i - c * 25;
        sm[OFF_W1T + k * 12 + c] = w1[i];
    }
    // b1 packed pairs: b1t[((j*8+xx)*8 + y)*2 + lh] = b1[(2j+lh)*64 + y*8+xx]
    for (int i = t; i < 768; i += THREADS) {
        int i2 = i >> 1, lh = i & 1;
        int j = i2 >> 6, rem = i2 & 63, xx = rem >> 3, y = rem & 7;
        sm[OFF_B1T + i] = b1[(2 * j + lh) * 64 + y * 8 + xx];
    }
    // w2t[k*96 + o*8 + j] = w2[o*200 + j*25 + k]  (j = o's 8 inputs, ascending c)
    for (int i = t; i < 2400; i += THREADS) {
        int k = i / 96, rem = i - k * 96, o = rem >> 3, j = rem & 7;
        sm[OFF_W2T + i] = w2[o * 200 + j * 25 + k];
    }
    for (int i = t; i < 192; i += THREADS) sm[OFF_H2B + i] = b2[i];
    // w3t[h*192 + k] = w3[k*30 + h]
    for (int i = t; i < 5760; i += THREADS) {
        int k = i / 30, h = i - k * 30;
        sm[OFF_W3T + h * 192 + k] = w3[i];
    }
    for (int i = t; i < 30;  i += THREADS) sm[OFF_H3B + i]  = b3[i];
    for (int i = t; i < 300; i += THREADS) sm[OFF_OUTW + i] = wo[i];
    for (int i = t; i < 10;  i += THREADS) sm[OFF_OUTB + i] = bo[i];
    if (t < 20) sm[OFF_NEG + t] = -1.0f;
    __syncthreads();

    // ---------------- Phase B: conv1, thread = (sample, row), all 8 cols -----
    {
        int s = t >> 3, y = t & 7;
        const float* sin_ = &sm[OFF_R2 + s * SIN_STR];
        const float* negrow = &sm[OFF_NEG];

        ull A[48];                                  // [xx][6 ch-pairs]
#pragma unroll
        for (int xx = 0; xx < 8; xx++)
#pragma unroll
            for (int j = 0; j < 6; j++)
                A[xx * 6 + j] = *(const ull*)&sm[OFF_B1T + ((j * 8 + xx) * 8 + y) * 2];

        for (int ky = 0; ky < 5; ky++) {
            int r = 2 * y + ky - 2;
            const float4* rowp = (const float4*)
                (((unsigned)r < 16u) ? (sin_ + r * 20) : negrow);
            float v[20];
            float4 l0 = rowp[0], l1 = rowp[1], l2 = rowp[2], l3 = rowp[3], l4 = rowp[4];
            v[0]=l0.x; v[1]=l0.y; v[2]=l0.z; v[3]=l0.w;
            v[4]=l1.x; v[5]=l1.y; v[6]=l1.z; v[7]=l1.w;
            v[8]=l2.x; v[9]=l2.y; v[10]=l2.z; v[11]=l2.w;
            v[12]=l3.x; v[13]=l3.y; v[14]=l3.z; v[15]=l3.w;
            v[16]=l4.x; v[17]=l4.y; v[18]=l4.z; v[19]=l4.w;
#pragma unroll
            for (int kx = 0; kx < 5; kx++) {
                const ulonglong2* wp =
                    (const ulonglong2*)&sm[OFF_W1T + (ky * 5 + kx) * 12];
                ulonglong2 p0 = wp[0], p1 = wp[1], p2 = wp[2];
#pragma unroll
                for (int xx = 0; xx < 8; xx++) {
                    float vs = v[2 * xx + kx];
                    ull vv = pk2(vs, vs);
                    fma2(A[xx*6+0], vv, p0.x); fma2(A[xx*6+1], vv, p0.y);
                    fma2(A[xx*6+2], vv, p1.x); fma2(A[xx*6+3], vv, p1.y);
                    fma2(A[xx*6+4], vv, p2.x); fma2(A[xx*6+5], vv, p2.y);
                }
            }
        }
        // relu + store channel-minor [y][xx][12], 3x STS.128 per column
        float* c1s = &sm[OFF_C1 + s * C1STR];
#pragma unroll
        for (int xx = 0; xx < 8; xx++) {
            float f[12];
#pragma unroll
            for (int j = 0; j < 6; j++) unpk2(A[xx * 6 + j], f[2 * j], f[2 * j + 1]);
#pragma unroll
            for (int c = 0; c < 12; c++) f[c] = f[c] > 0.0f ? f[c] : 0.0f;
            float4* dst = (float4*)&c1s[y * 100 + xx * 12];
            dst[0] = make_float4(f[0], f[1], f[2],  f[3]);
            dst[1] = make_float4(f[4], f[5], f[6],  f[7]);
            dst[2] = make_float4(f[8], f[9], f[10], f[11]);
        }
    }
    __syncthreads();

    // -------- Phase C: conv2, ALL 256 threads, warp = sample-group -----------
    // warp w (= t>>5) handles samples {w, w+8, w+16, w+24}.
    // lanes 0-15: ohalf=0 -> o in {0,1,4,5,8,9};  lanes 16-31: ohalf=1 -> {2,3,6,7,10,11}
    // o = g*4 + ohalf*2 + l  (g = act-pair group, l = 0/1) -> warp-uniform code,
    // act loads identical across lane halves (dedup), 6 o x 4 samples per thread.
    {
        int w = t >> 5;                 // 0..7 = sp
        int lane = t & 31;
        int ohalf = lane >> 4;          // 0/1
        int pos = lane & 15;
        int ii = pos >> 2, jj = pos & 3;
        const float* c1a = &sm[OFF_C1 + w * C1STR];
        const float* c1b = &sm[OFF_C1 + (w + 8) * C1STR];
        const float* c1c = &sm[OFF_C1 + (w + 16) * C1STR];
        const float* c1d = &sm[OFF_C1 + (w + 24) * C1STR];
        const float* negrow = &sm[OFF_NEG];

        ull ac[24];                     // [oi 0..5][sample 0..3]
#pragma unroll
        for (int i = 0; i < 24; i++) ac[i] = 0;

#pragma unroll
        for (int ky = 0; ky < 5; ky++) {
            int yy = 2 * ii + ky - 2;
#pragma unroll
            for (int kx = 0; kx < 5; kx++) {
                int xx2 = 2 * jj + kx - 2;
                bool ok = ((unsigned)yy < 8u) && ((unsigned)xx2 < 8u);
                int ad = yy * 100 + xx2 * 12;
                const ulonglong2* pa = (const ulonglong2*)(ok ? (c1a + ad) : negrow);
                const ulonglong2* pb = (const ulonglong2*)(ok ? (c1b + ad) : negrow);
                const ulonglong2* pc = (const ulonglong2*)(ok ? (c1c + ad) : negrow);
                const ulonglong2* pd = (const ulonglong2*)(ok ? (c1d + ad) : negrow);
                ulonglong2 qa0 = pa[0], qa1 = pa[1], qa2 = pa[2];
                ulonglong2 qb0 = pb[0], qb1 = pb[1], qb2 = pb[2];
                ulonglong2 qc0 = pc[0], qc1 = pc[1], qc2 = pc[2];
                ulonglong2 qd0 = pd[0], qd1 = pd[1], qd2 = pd[2];
                ull a0[6] = {qa0.x, qa0.y, qa1.x, qa1.y, qa2.x, qa2.y};
                ull b0[6] = {qb0.x, qb0.y, qb1.x, qb1.y, qb2.x, qb2.y};
                ull c0[6] = {qc0.x, qc0.y, qc1.x, qc1.y, qc2.x, qc2.y};
                ull d0[6] = {qd0.x, qd0.y, qd1.x, qd1.y, qd2.x, qd2.y};
                int k = ky * 5 + kx;
                const float* wbase = &sm[OFF_W2T + k * 96 + ohalf * 16];
#pragma unroll
                for (int g = 0; g < 3; g++) {
                    const int p0 = (g == 1) ? 2 : 0;
                    const int p1 = (g == 0) ? 2 : 4;
#pragma unroll
                    for (int l = 0; l < 2; l++) {
                        const int oi = g * 2 + l;
                        const ulonglong2* wp =
                            (const ulonglong2*)(wbase + g * 32 + l * 8);
                        ulonglong2 wA = wp[0], wB = wp[1];
                        fma2(ac[oi*4+0], a0[p0], wA.x); fma2(ac[oi*4+0], a0[p0+1], wA.y);
                        fma2(ac[oi*4+0], a0[p1], wB.x); fma2(ac[oi*4+0], a0[p1+1], wB.y);
                        fma2(ac[oi*4+1], b0[p0], wA.x); fma2(ac[oi*4+1], b0[p0+1], wA.y);
                        fma2(ac[oi*4+1], b0[p1], wB.x); fma2(ac[oi*4+1], b0[p1+1], wB.y);
                        fma2(ac[oi*4+2], c0[p0], wA.x); fma2(ac[oi*4+2], c0[p0+1], wA.y);
                        fma2(ac[oi*4+2], c0[p1], wB.x); fma2(ac[oi*4+2], c0[p1+1], wB.y);
                        fma2(ac[oi*4+3], d0[p0], wA.x); fma2(ac[oi*4+3], d0[p0+1], wA.y);
                        fma2(ac[oi*4+3], d0[p1], wB.x); fma2(ac[oi*4+3], d0[p1+1], wB.y);
                    }
                }
            }
        }
        // bias + relu + transposed store out2t[k][33 + s]
        float* o2 = &sm[OFF_R2];
#pragma unroll
        for (int g = 0; g < 3; g++)
#pragma unroll
            for (int l = 0; l < 2; l++) {
                const int oi = g * 2 + l;
                int o = g * 4 + ohalf * 2 + l;
                float bias = sm[OFF_H2B + o * 16 + pos];
                int kk = (o * 16 + pos) * O2STR;
                float lo, hi;
                unpk2(ac[oi*4+0], lo, hi); float va = lo + hi + bias;
                unpk2(ac[oi*4+1], lo, hi); float vb = lo + hi + bias;
                unpk2(ac[oi*4+2], lo, hi); float vc = lo + hi + bias;
                unpk2(ac[oi*4+3], lo, hi); float vd = lo + hi + bias;
                o2[kk + w]      = va > 0.0f ? va : 0.0f;
                o2[kk + w + 8]  = vb > 0.0f ? vb : 0.0f;
                o2[kk + w + 16] = vc > 0.0f ? vc : 0.0f;
                o2[kk + w + 24] = vd > 0.0f ? vd : 0.0f;
            }
    }
    __syncthreads();

    // -------- Phase D: fc1 192->30 + relu (4 samples x 2 h / thread) ---------
    if (t < 120) {
        int h2 = t >> 3, sp = t & 7;                // h2 0..14, samples sp,+8,+16,+24
        int h0 = 2 * h2, h1 = h0 + 1;
        const float* o2 = &sm[OFF_R2];
        const ulonglong2* wp0 = (const ulonglong2*)&sm[OFF_W3T + h0 * 192];
        const ulonglong2* wp1 = (const ulonglong2*)&sm[OFF_W3T + h1 * 192];
        ull s0[4] = {0, 0, 0, 0};                   // h0 x 4 samples
        ull s1[4] = {0, 0, 0, 0};                   // h1 x 4 samples
#pragma unroll 4
        for (int k4 = 0; k4 < 48; k4++) {
            ulonglong2 wa = wp0[k4], wb = wp1[k4];
            int k = 4 * k4;
#pragma unroll
            for (int q = 0; q < 4; q++) {
                int s = sp + q * 8;
                float a0 = o2[(k+0)*O2STR + s], a1 = o2[(k+1)*O2STR + s];
                float a2 = o2[(k+2)*O2STR + s], a3 = o2[(k+3)*O2STR + s];
                ull v01 = pk2(a0, a1), v23 = pk2(a2, a3);
                fma2(s0[q], v01, wa.x); fma2(s0[q], v23, wa.y);
                fma2(s1[q], v01, wb.x); fma2(s1[q], v23, wb.y);
            }
        }
        float bb0 = sm[OFF_H3B + h0], bb1 = sm[OFF_H3B + h1];
#pragma unroll
        for (int q = 0; q < 4; q++) {
            int s = sp + q * 8;
            float lo, hi;
            unpk2(s0[q], lo, hi); float v0 = lo + hi + bb0;
            unpk2(s1[q], lo, hi); float v1 = lo + hi + bb1;
            sm[OFF_HID + s * 32 + h0] = v0 > 0.0f ? v0 : 0.0f;
            sm[OFF_HID + s * 32 + h1] = v1 > 0.0f ? v1 : 0.0f;
        }
    }
    __syncthreads();

    // ---------------- Phase E: fc2 30->10 (2 samples/thread) -----------------
    if (t < 160) {
        int s = t / 10, o = t - s * 10;
        float sum0 = sm[OFF_OUTB + o], sum1 = sum0;
        const float* h0 = &sm[OFF_HID + s * 32];
        const float* h1 = &sm[OFF_HID + (s + 16) * 32];
#pragma unroll
        for (int h = 0; h < 30; h++) {
            float w = sm[OFF_OUTW + h * 10 + o];
            sum0 += h0[h] * w;
            sum1 += h1[h] * w;
        }
        long g0 = base_s + s, g1 = base_s + s + 16;
        if (g0 < nsamp) out[g0 * 10 + o] = sum0;
        if (g1 < nsamp) out[g1 * 10 + o] = sum1;
    }
}

extern "C" void kernel_launch(void* const* d_in, const int* in_sizes, int n_in,
                              void* d_out, int out_size)
{
    const float* x  = (const float*)d_in[0];
    const float* w1 = (const float*)d_in[1];
    const float* b1 = (const float*)d_in[2];
    const float* w2 = (const float*)d_in[3];
    const float* b2 = (const float*)d_in[4];
    const float* w3 = (const float*)d_in[5];
    const float* b3 = (const float*)d_in[6];
    const float* wo = (const float*)d_in[7];
    const float* bo = (const float*)d_in[8];
    float* out = (float*)d_out;

    int nsamp = in_sizes[0] / 256;                       // 131072
    int grid  = (nsamp + SAMPLES - 1) / SAMPLES;         // 4096
    size_t smem = SMEM_FLOATS * sizeof(float);           // 184080 B

    cudaFuncSetAttribute(modernnet_fused_kernel,
                         cudaFuncAttributeMaxDynamicSharedMemorySize, (int)smem);
    modernnet_fused_kernel<<<grid, THREADS, smem>>>(x, w1, b1, w2, b2, w3, b3,
                                                    wo, bo, out, nsamp);
}

// round 16
// speedup vs baseline: 1.1264x; 1.1264x over previous
#include <cuda_runtime.h>

#define SAMPLES 32
#define THREADS 256

#define SIN_STR 324    // staged input per-sample stride: 16 rows x 20 cols (+4 pad)
#define C1STR   808    // conv1-out per-sample stride: [y][8 xx][12 ch] rows of 100 (+8 pad)
#define O2STR   33     // conv2-out transposed: [192 k][33]

enum {
    OFF_C1   = 0,                          // 32 * 808 = 25856
    OFF_R2   = 32 * C1STR,                 // 25856: input stage (32*324=10368), later out2t
    OFF_HID  = OFF_R2 + 192 * O2STR,       // 32192 (+1024 = 33216 <= 36224, inside stage)
    OFF_W1T  = OFF_R2 + 32 * SIN_STR,      // 36224: w1 [25 tap][12 ch]
    OFF_B1T  = OFF_W1T + 304,              // 36528: b1 pairs [6 j][8 xx][8 y][2]
    OFF_W2T  = OFF_B1T + 768,              // 37296: w2 [26 tap][12 o][8 j] (tap 25 = zeros)
    OFF_H2B  = OFF_W2T + 2496,             // 39792: [12][16]
    OFF_W3T  = OFF_H2B + 192,              // 39984: w3 [30 h][192 k]
    OFF_H3B  = OFF_W3T + 5760,             // 45744
    OFF_OUTW = OFF_H3B + 32,               // 45776: [30][10]
    OFF_OUTB = OFF_OUTW + 304,             // 46080
    OFF_NEG  = OFF_OUTB + 16,              // 46096: 20 floats of -1 (shared pad row)
    SMEM_FLOATS = OFF_NEG + 20             // 46116 floats = 184464 B
};

typedef unsigned long long ull;

__device__ __forceinline__ ull pk2(float a, float b) {
    ull r; asm("mov.b64 %0, {%1, %2};" : "=l"(r) : "f"(a), "f"(b)); return r;
}
__device__ __forceinline__ void fma2(ull& d, ull a, ull b) {
    asm("fma.rn.f32x2 %0, %1, %2, %0;" : "+l"(d) : "l"(a), "l"(b));
}
__device__ __forceinline__ void unpk2(ull v, float& lo, float& hi) {
    asm("mov.b64 {%0, %1}, %2;" : "=f"(lo), "=f"(hi) : "l"(v));
}

__global__ void __launch_bounds__(THREADS, 1)
modernnet_fused_kernel(const float* __restrict__ x,
                       const float* __restrict__ w1,   // [12,1,5,5]
                       const float* __restrict__ b1,   // [12,8,8]
                       const float* __restrict__ w2,   // [12,8,5,5]
                       const float* __restrict__ b2,   // [12,4,4]
                       const float* __restrict__ w3,   // [192,30]
                       const float* __restrict__ b3,   // [30]
                       const float* __restrict__ wo,   // [30,10]
                       const float* __restrict__ bo,   // [10]
                       float* __restrict__ out,        // [B,10]
                       int nsamp)
{
    extern __shared__ float sm[];
    const int t = threadIdx.x;
    const long base_s = (long)blockIdx.x * SAMPLES;

    // ---------------- Phase A: stage input (with -1 halo) + weights ----------
    for (int i = t; i < SAMPLES * 320; i += THREADS) {
        int s = i / 320, rem = i - s * 320;
        int r = rem / 20, c20 = rem - r * 20;
        int cc = c20 - 2;                       // halo cols -2..17
        long gs = base_s + s;
        float v = -1.0f;
        if ((unsigned)cc < 16u && gs < nsamp) v = x[gs * 256 + r * 16 + cc];
        sm[OFF_R2 + s * SIN_STR + r * 20 + c20] = v;
    }
    // w1t[k*12 + c] = w1[c*25 + k]
    for (int i = t; i < 300; i += THREADS) {
        int c = i / 25, k = i - c * 25;
        sm[OFF_W1T + k * 12 + c] = w1[i];
    }
    // b1 packed pairs: b1t[((j*8+xx)*8 + y)*2 + lh] = b1[(2j+lh)*64 + y*8+xx]
    for (int i = t; i < 768; i += THREADS) {
        int i2 = i >> 1, lh = i & 1;
        int j = i2 >> 6, rem = i2 & 63, xx = rem >> 3, y = rem & 7;
        sm[OFF_B1T + i] = b1[(2 * j + lh) * 64 + y * 8 + xx];
    }
    // w2t[k*96 + o*8 + j] = w2[o*200 + j*25 + k]; tap k=25 zero-padded
    for (int i = t; i < 2496; i += THREADS) {
        int k = i / 96, rem = i - k * 96, o = rem >> 3, j = rem & 7;
        sm[OFF_W2T + i] = (k < 25) ? w2[o * 200 + j * 25 + k] : 0.0f;
    }
    for (int i = t; i < 192; i += THREADS) sm[OFF_H2B + i] = b2[i];
    // w3t[h*192 + k] = w3[k*30 + h]
    for (int i = t; i < 5760; i += THREADS) {
        int k = i / 30, h = i - k * 30;
        sm[OFF_W3T + h * 192 + k] = w3[i];
    }
    for (int i = t; i < 30;  i += THREADS) sm[OFF_H3B + i]  = b3[i];
    for (int i = t; i < 300; i += THREADS) sm[OFF_OUTW + i] = wo[i];
    for (int i = t; i < 10;  i += THREADS) sm[OFF_OUTB + i] = bo[i];
    if (t < 20) sm[OFF_NEG + t] = -1.0f;
    __syncthreads();

    // ---------------- Phase B: conv1, thread = (sample, row), all 8 cols -----
    {
        int s = t >> 3, y = t & 7;
        const float* sin_ = &sm[OFF_R2 + s * SIN_STR];
        const float* negrow = &sm[OFF_NEG];

        ull A[48];                                  // [xx][6 ch-pairs]
#pragma unroll
        for (int xx = 0; xx < 8; xx++)
#pragma unroll
            for (int j = 0; j < 6; j++)
                A[xx * 6 + j] = *(const ull*)&sm[OFF_B1T + ((j * 8 + xx) * 8 + y) * 2];

        for (int ky = 0; ky < 5; ky++) {
            int r = 2 * y + ky - 2;
            const float4* rowp = (const float4*)
                (((unsigned)r < 16u) ? (sin_ + r * 20) : negrow);
            float v[20];
            float4 l0 = rowp[0], l1 = rowp[1], l2 = rowp[2], l3 = rowp[3], l4 = rowp[4];
            v[0]=l0.x; v[1]=l0.y; v[2]=l0.z; v[3]=l0.w;
            v[4]=l1.x; v[5]=l1.y; v[6]=l1.z; v[7]=l1.w;
            v[8]=l2.x; v[9]=l2.y; v[10]=l2.z; v[11]=l2.w;
            v[12]=l3.x; v[13]=l3.y; v[14]=l3.z; v[15]=l3.w;
            v[16]=l4.x; v[17]=l4.y; v[18]=l4.z; v[19]=l4.w;
#pragma unroll
            for (int kx = 0; kx < 5; kx++) {
                const ulonglong2* wp =
                    (const ulonglong2*)&sm[OFF_W1T + (ky * 5 + kx) * 12];
                ulonglong2 p0 = wp[0], p1 = wp[1], p2 = wp[2];
#pragma unroll
                for (int xx = 0; xx < 8; xx++) {
                    float vs = v[2 * xx + kx];
                    ull vv = pk2(vs, vs);
                    fma2(A[xx*6+0], vv, p0.x); fma2(A[xx*6+1], vv, p0.y);
                    fma2(A[xx*6+2], vv, p1.x); fma2(A[xx*6+3], vv, p1.y);
                    fma2(A[xx*6+4], vv, p2.x); fma2(A[xx*6+5], vv, p2.y);
                }
            }
        }
        // relu + store channel-minor [y][xx][12], 3x STS.128 per column
        float* c1s = &sm[OFF_C1 + s * C1STR];
#pragma unroll
        for (int xx = 0; xx < 8; xx++) {
            float f[12];
#pragma unroll
            for (int j = 0; j < 6; j++) unpk2(A[xx * 6 + j], f[2 * j], f[2 * j + 1]);
#pragma unroll
            for (int c = 0; c < 12; c++) f[c] = f[c] > 0.0f ? f[c] : 0.0f;
            float4* dst = (float4*)&c1s[y * 100 + xx * 12];
            dst[0] = make_float4(f[0], f[1], f[2],  f[3]);
            dst[1] = make_float4(f[4], f[5], f[6],  f[7]);
            dst[2] = make_float4(f[8], f[9], f[10], f[11]);
        }
    }
    __syncthreads();

    // -------- Phase C: conv2, 256 threads, warp = sample-quad, taps split ----
    // warp w handles samples {w, w+8, w+16, w+24}; lane = (khalf, pos).
    // khalf 0 -> taps 0,2,..,24 ; khalf 1 -> taps 1,3,..,23,25(zero-pad).
    // 13 uniform iterations, k = 2*i + khalf; partial sums combined via shfl.
    {
        int w = t >> 5;                 // 0..7 = sp
        int lane = t & 31;
        int khalf = lane >> 4;          // 0/1
        int pos = lane & 15;
        int ii = pos >> 2, jj = pos & 3;
        const float* c1a = &sm[OFF_C1 + w * C1STR];
        const float* c1b = &sm[OFF_C1 + (w + 8) * C1STR];
        const float* c1c = &sm[OFF_C1 + (w + 16) * C1STR];
        const float* c1d = &sm[OFF_C1 + (w + 24) * C1STR];
        const float* negrow = &sm[OFF_NEG];

        ull ac[48];                     // [o][sample]
#pragma unroll
        for (int i = 0; i < 48; i++) ac[i] = 0;

#pragma unroll
        for (int i = 0; i < 13; i++) {
            int k = 2 * i + khalf;                  // 0..25
            int ky = k / 5, kx = k - 5 * ky;        // ky<=5 (k=25 -> zero weights)
            int yy = 2 * ii + ky - 2;
            int xx2 = 2 * jj + kx - 2;
            bool ok = ((unsigned)yy < 8u) && ((unsigned)xx2 < 8u);
            int ad = yy * 100 + xx2 * 12;
            const ulonglong2* pa = (const ulonglong2*)(ok ? (c1a + ad) : negrow);
            const ulonglong2* pb = (const ulonglong2*)(ok ? (c1b + ad) : negrow);
            const ulonglong2* pc = (const ulonglong2*)(ok ? (c1c + ad) : negrow);
            const ulonglong2* pd = (const ulonglong2*)(ok ? (c1d + ad) : negrow);
            ulonglong2 qa0 = pa[0], qa1 = pa[1], qa2 = pa[2];
            ulonglong2 qb0 = pb[0], qb1 = pb[1], qb2 = pb[2];
            ulonglong2 qc0 = pc[0], qc1 = pc[1], qc2 = pc[2];
            ulonglong2 qd0 = pd[0], qd1 = pd[1], qd2 = pd[2];
            ull a0[6] = {qa0.x, qa0.y, qa1.x, qa1.y, qa2.x, qa2.y};
            ull b0[6] = {qb0.x, qb0.y, qb1.x, qb1.y, qb2.x, qb2.y};
            ull c0[6] = {qc0.x, qc0.y, qc1.x, qc1.y, qc2.x, qc2.y};
            ull d0[6] = {qd0.x, qd0.y, qd1.x, qd1.y, qd2.x, qd2.y};
            const float* wbase = &sm[OFF_W2T + k * 96];
#pragma unroll
            for (int o = 0; o < 12; o++) {
                const int p0 = (o < 8) ? ((o < 4) ? 0 : 2) : 0;
                const int p1 = (o < 4) ? 2 : 4;
                const ulonglong2* wp = (const ulonglong2*)(wbase + o * 8);
                ulonglong2 wA = wp[0], wB = wp[1];
                fma2(ac[o*4+0], a0[p0], wA.x); fma2(ac[o*4+0], a0[p0+1], wA.y);
                fma2(ac[o*4+0], a0[p1], wB.x); fma2(ac[o*4+0], a0[p1+1], wB.y);
                fma2(ac[o*4+1], b0[p0], wA.x); fma2(ac[o*4+1], b0[p0+1], wA.y);
                fma2(ac[o*4+1], b0[p1], wB.x); fma2(ac[o*4+1], b0[p1+1], wB.y);
                fma2(ac[o*4+2], c0[p0], wA.x); fma2(ac[o*4+2], c0[p0+1], wA.y);
                fma2(ac[o*4+2], c0[p1], wB.x); fma2(ac[o*4+2], c0[p1+1], wB.y);
                fma2(ac[o*4+3], d0[p0], wA.x); fma2(ac[o*4+3], d0[p0+1], wA.y);
                fma2(ac[o*4+3], d0[p1], wB.x); fma2(ac[o*4+3], d0[p1+1], wB.y);
            }
        }
        // cross-half reduce + bias + relu + transposed store (khalf 0 stores)
        float* o2 = &sm[OFF_R2];
#pragma unroll
        for (int o = 0; o < 12; o++) {
            float bias = sm[OFF_H2B + o * 16 + pos];
            int kk = (o * 16 + pos) * O2STR;
#pragma unroll
            for (int q = 0; q < 4; q++) {
                float lo, hi;
                unpk2(ac[o * 4 + q], lo, hi);
                float r = lo + hi;
                r += __shfl_xor_sync(0xffffffffu, r, 16);
                float v = r + bias;
                if (khalf == 0)
                    o2[kk + w + q * 8] = v > 0.0f ? v : 0.0f;
            }
        }
    }
    __syncthreads();

    // -------- Phase D: fc1 192->30 + relu (4 samples x 2 h / thread) ---------
    if (t < 120) {
        int h2 = t >> 3, sp = t & 7;                // h2 0..14, samples sp,+8,+16,+24
        int h0 = 2 * h2, h1 = h0 + 1;
        const float* o2 = &sm[OFF_R2];
        const ulonglong2* wp0 = (const ulonglong2*)&sm[OFF_W3T + h0 * 192];
        const ulonglong2* wp1 = (const ulonglong2*)&sm[OFF_W3T + h1 * 192];
        ull s0[4] = {0, 0, 0, 0};                   // h0 x 4 samples
        ull s1[4] = {0, 0, 0, 0};                   // h1 x 4 samples
#pragma unroll 4
        for (int k4 = 0; k4 < 48; k4++) {
            ulonglong2 wa = wp0[k4], wb = wp1[k4];
            int k = 4 * k4;
#pragma unroll
            for (int q = 0; q < 4; q++) {
                int s = sp + q * 8;
                float a0 = o2[(k+0)*O2STR + s], a1 = o2[(k+1)*O2STR + s];
                float a2 = o2[(k+2)*O2STR + s], a3 = o2[(k+3)*O2STR + s];
                ull v01 = pk2(a0, a1), v23 = pk2(a2, a3);
                fma2(s0[q], v01, wa.x); fma2(s0[q], v23, wa.y);
                fma2(s1[q], v01, wb.x); fma2(s1[q], v23, wb.y);
            }
        }
        float bb0 = sm[OFF_H3B + h0], bb1 = sm[OFF_H3B + h1];
#pragma unroll
        for (int q = 0; q < 4; q++) {
            int s = sp + q * 8;
            float lo, hi;
            unpk2(s0[q], lo, hi); float v0 = lo + hi + bb0;
            unpk2(s1[q], lo, hi); float v1 = lo + hi + bb1;
            sm[OFF_HID + s * 32 + h0] = v0 > 0.0f ? v0 : 0.0f;
            sm[OFF_HID + s * 32 + h1] = v1 > 0.0f ? v1 : 0.0f;
        }
    }
    __syncthreads();

    // ---------------- Phase E: fc2 30->10 (2 samples/thread) -----------------
    if (t < 160) {
        int s = t / 10, o = t - s * 10;
        float sum0 = sm[OFF_OUTB + o], sum1 = sum0;
        const float* h0 = &sm[OFF_HID + s * 32];
        const float* h1 = &sm[OFF_HID + (s + 16) * 32];
#pragma unroll
        for (int h = 0; h < 30; h++) {
            float w = sm[OFF_OUTW + h * 10 + o];
            sum0 += h0[h] * w;
            sum1 += h1[h] * w;
        }
        long g0 = base_s + s, g1 = base_s + s + 16;
        if (g0 < nsamp) out[g0 * 10 + o] = sum0;
        if (g1 < nsamp) out[g1 * 10 + o] = sum1;
    }
}

extern "C" void kernel_launch(void* const* d_in, const int* in_sizes, int n_in,
                              void* d_out, int out_size)
{
    const float* x  = (const float*)d_in[0];
    const float* w1 = (const float*)d_in[1];
    const float* b1 = (const float*)d_in[2];
    const float* w2 = (const float*)d_in[3];
    const float* b2 = (const float*)d_in[4];
    const float* w3 = (const float*)d_in[5];
    const float* b3 = (const float*)d_in[6];
    const float* wo = (const float*)d_in[7];
    const float* bo = (const float*)d_in[8];
    float* out = (float*)d_out;

    int nsamp = in_sizes[0] / 256;                       // 131072
    int grid  = (nsamp + SAMPLES - 1) / SAMPLES;         // 4096
    size_t smem = SMEM_FLOATS * sizeof(float);           // 184464 B

    cudaFuncSetAttribute(modernnet_fused_kernel,
                         cudaFuncAttributeMaxDynamicSharedMemorySize, (int)smem);
    modernnet_fused_kernel<<<grid, THREADS, smem>>>(x, w1, b1, w2, b2, w3, b3,
                                                    wo, bo, out, nsamp);
}

// round 17
// speedup vs baseline: 1.3048x; 1.1584x over previous
#include <cuda_runtime.h>
#include <cuda_fp16.h>

#define SAMPLES 48
#define THREADS 384

#define SINH   324     // fp16 staged input per-sample stride in HALVES (16x20+4)
#define C1STR  808     // conv1-out per-sample stride fp32: [y][8 xx][12 ch] rows of 100
#define O2STR  49      // conv2-out transposed: [192 k][49]

enum {
    OFF_C1   = 0,                          // 48*808 = 38784 fl
    OFF_O2   = 0,                          // overlay (after conv2 sync): 192*49 = 9408
    OFF_HID  = 16384,                      // 48*32 = 1536 (inside C1 region, after o2)
    OFF_STG  = 38784,                      // fp16 input stage: 48*324 halves = 7776 fl
    OFF_W1T  = 46560,                      // w1 [25 tap][12 ch] = 300
    OFF_B1T  = 46860,                      // b1 pairs [6 j][8 xx][8 y][2] = 768
    OFF_W2T  = 47628,                      // w2 [26 tap][12 o][8 j] = 2496 (tap 25 zero)
    OFF_H2B  = 50124,                      // [12][16] = 192
    OFF_W3T  = 50316,                      // w3 [30 h][192 k] = 5760
    OFF_H3B  = 56076,                      // 32
    OFF_OUTW = 56108,                      // 304
    OFF_OUTB = 56412,                      // 16
    OFF_NEG  = 56428,                      // 20 fp32 -1 (conv2 OOB row)
    OFF_NEGH = 56448,                      // 16 halves -1 (conv1 OOB row) = 8 fl
    SMEM_FLOATS = 56456                    // 225824 B (<= 227KB opt-in), 1 block/SM
};

typedef unsigned long long ull;

__device__ __forceinline__ ull pk2(float a, float b) {
    ull r; asm("mov.b64 %0, {%1, %2};" : "=l"(r) : "f"(a), "f"(b)); return r;
}
__device__ __forceinline__ void fma2(ull& d, ull a, ull b) {
    asm("fma.rn.f32x2 %0, %1, %2, %0;" : "+l"(d) : "l"(a), "l"(b));
}
__device__ __forceinline__ void unpk2(ull v, float& lo, float& hi) {
    asm("mov.b64 {%0, %1}, %2;" : "=f"(lo), "=f"(hi) : "l"(v));
}
__device__ __forceinline__ void h2u_to_2f(unsigned u, float& a, float& b) {
    __half2 h = *reinterpret_cast<__half2*>(&u);
    float2 f = __half22float2(h);
    a = f.x; b = f.y;
}

__global__ void __launch_bounds__(THREADS, 1)
modernnet_fused_kernel(const float* __restrict__ x,
                       const float* __restrict__ w1,   // [12,1,5,5]
                       const float* __restrict__ b1,   // [12,8,8]
                       const float* __restrict__ w2,   // [12,8,5,5]
                       const float* __restrict__ b2,   // [12,4,4]
                       const float* __restrict__ w3,   // [192,30]
                       const float* __restrict__ b3,   // [30]
                       const float* __restrict__ wo,   // [30,10]
                       const float* __restrict__ bo,   // [10]
                       float* __restrict__ out,        // [B,10]
                       int nsamp)
{
    extern __shared__ float sm[];
    __half* stageh = reinterpret_cast<__half*>(sm + OFF_STG);
    const int t = threadIdx.x;
    const long base_s = (long)blockIdx.x * SAMPLES;

    // ------------- Phase A: stage input (fp16, -1 col halo) + weights --------
    for (int i = t; i < SAMPLES * 320; i += THREADS) {
        int s = i / 320, rem = i - s * 320;
        int r = rem / 20, c20 = rem - r * 20;
        int cc = c20 - 2;                       // halo cols -2..17
        long gs = base_s + s;
        float v = -1.0f;
        if ((unsigned)cc < 16u && gs < nsamp) v = x[gs * 256 + r * 16 + cc];
        stageh[s * SINH + r * 20 + c20] = __float2half(v);
    }
    for (int i = t; i < 300; i += THREADS) {            // w1t[k*12+c] = w1[c*25+k]
        int c = i / 25, k = i - c * 25;
        sm[OFF_W1T + k * 12 + c] = w1[i];
    }
    for (int i = t; i < 768; i += THREADS) {            // b1 pairs
        int i2 = i >> 1, lh = i & 1;
        int j = i2 >> 6, rem = i2 & 63, xx = rem >> 3, y = rem & 7;
        sm[OFF_B1T + i] = b1[(2 * j + lh) * 64 + y * 8 + xx];
    }
    for (int i = t; i < 2496; i += THREADS) {           // w2t, tap 25 zero-padded
        int k = i / 96, rem = i - k * 96, o = rem >> 3, j = rem & 7;
        sm[OFF_W2T + i] = (k < 25) ? w2[o * 200 + j * 25 + k] : 0.0f;
    }
    for (int i = t; i < 192; i += THREADS) sm[OFF_H2B + i] = b2[i];
    for (int i = t; i < 5760; i += THREADS) {           // w3t[h*192+k]
        int k = i / 30, h = i - k * 30;
        sm[OFF_W3T + h * 192 + k] = w3[i];
    }
    for (int i = t; i < 30;  i += THREADS) sm[OFF_H3B + i]  = b3[i];
    for (int i = t; i < 300; i += THREADS) sm[OFF_OUTW + i] = wo[i];
    for (int i = t; i < 10;  i += THREADS) sm[OFF_OUTB + i] = bo[i];
    if (t < 20) sm[OFF_NEG + t] = -1.0f;
    if (t < 16) reinterpret_cast<__half*>(sm + OFF_NEGH)[t] = __float2half(-1.0f);
    __syncthreads();

    // -------- Phase B: conv1, 2 passes x 24 samples, thread=(s,y,xh) ---------
#pragma unroll
    for (int ph = 0; ph < 2; ph++) {
        int s   = ph * 24 + (t >> 4);
        int sub = t & 15;
        int y = sub & 7, xh = sub >> 3;
        const __half* sinh_ = stageh + s * SINH;
        const __half* negh  = reinterpret_cast<const __half*>(sm + OFF_NEGH);

        ull A[24];                                  // [lx][6 ch-pairs]
#pragma unroll
        for (int lx = 0; lx < 4; lx++)
#pragma unroll
            for (int j = 0; j < 6; j++)
                A[lx * 6 + j] =
                    *(const ull*)&sm[OFF_B1T + ((j * 8 + (xh * 4 + lx)) * 8 + y) * 2];

#pragma unroll
        for (int ky = 0; ky < 5; ky++) {
            int r = 2 * y + ky - 2;
            const __half* rb = ((unsigned)r < 16u) ? (sinh_ + r * 20 + xh * 8)
                                                   : negh;
            const uint2* rp = (const uint2*)rb;     // 12 halves
            uint2 u0 = rp[0], u1 = rp[1], u2 = rp[2];
            float v[12];
            h2u_to_2f(u0.x, v[0], v[1]);  h2u_to_2f(u0.y, v[2],  v[3]);
            h2u_to_2f(u1.x, v[4], v[5]);  h2u_to_2f(u1.y, v[6],  v[7]);
            h2u_to_2f(u2.x, v[8], v[9]);  h2u_to_2f(u2.y, v[10], v[11]);
#pragma unroll
            for (int kx = 0; kx < 5; kx++) {
                const ulonglong2* wp =
                    (const ulonglong2*)&sm[OFF_W1T + (ky * 5 + kx) * 12];
                ulonglong2 p0 = wp[0], p1 = wp[1], p2 = wp[2];
#pragma unroll
                for (int lx = 0; lx < 4; lx++) {
                    float vs = v[2 * lx + kx];
                    ull vv = pk2(vs, vs);
                    fma2(A[lx*6+0], vv, p0.x); fma2(A[lx*6+1], vv, p0.y);
                    fma2(A[lx*6+2], vv, p1.x); fma2(A[lx*6+3], vv, p1.y);
                    fma2(A[lx*6+4], vv, p2.x); fma2(A[lx*6+5], vv, p2.y);
                }
            }
        }
        // relu + store fp32 channel-minor [y][xx][12], 3x STS.128 per col
        float* c1s = &sm[OFF_C1 + s * C1STR];
#pragma unroll
        for (int lx = 0; lx < 4; lx++) {
            int xx = xh * 4 + lx;
            float f[12];
#pragma unroll
            for (int j = 0; j < 6; j++) unpk2(A[lx * 6 + j], f[2 * j], f[2 * j + 1]);
#pragma unroll
            for (int c = 0; c < 12; c++) f[c] = f[c] > 0.0f ? f[c] : 0.0f;
            float4* dst = (float4*)&c1s[y * 100 + xx * 12];
            dst[0] = make_float4(f[0], f[1], f[2],  f[3]);
            dst[1] = make_float4(f[4], f[5], f[6],  f[7]);
            dst[2] = make_float4(f[8], f[9], f[10], f[11]);
        }
    }
    __syncthreads();

    // -------- Phase C: conv2, 12 warps, warp = sample-quad, tap-split --------
    // warp w handles samples {w, w+12, w+24, w+36}; lane=(khalf,pos).
    // Results ride in regs across a sync, then store o2 overlaying dead C1.
    float vv[48];                                   // [o][q] final values
    {
        int w = t >> 5;                 // 0..11
        int lane = t & 31;
        int khalf = lane >> 4;
        int pos = lane & 15;
        int ii = pos >> 2, jj = pos & 3;
        const float* c1a = &sm[OFF_C1 + w * C1STR];
        const float* c1b = &sm[OFF_C1 + (w + 12) * C1STR];
        const float* c1c = &sm[OFF_C1 + (w + 24) * C1STR];
        const float* c1d = &sm[OFF_C1 + (w + 36) * C1STR];
        const float* negrow = &sm[OFF_NEG];

        ull ac[48];
#pragma unroll
        for (int i = 0; i < 48; i++) ac[i] = 0;

#pragma unroll
        for (int i = 0; i < 13; i++) {
            int k = 2 * i + khalf;                  // 0..25
            int ky = k / 5, kx = k - 5 * ky;
            int yy = 2 * ii + ky - 2;
            int xx2 = 2 * jj + kx - 2;
            bool ok = ((unsigned)yy < 8u) && ((unsigned)xx2 < 8u);
            int ad = yy * 100 + xx2 * 12;
            const ulonglong2* pa = (const ulonglong2*)(ok ? (c1a + ad) : negrow);
            const ulonglong2* pb = (const ulonglong2*)(ok ? (c1b + ad) : negrow);
            const ulonglong2* pc = (const ulonglong2*)(ok ? (c1c + ad) : negrow);
            const ulonglong2* pd = (const ulonglong2*)(ok ? (c1d + ad) : negrow);
            ulonglong2 qa0 = pa[0], qa1 = pa[1], qa2 = pa[2];
            ulonglong2 qb0 = pb[0], qb1 = pb[1], qb2 = pb[2];
            ulonglong2 qc0 = pc[0], qc1 = pc[1], qc2 = pc[2];
            ulonglong2 qd0 = pd[0], qd1 = pd[1], qd2 = pd[2];
            ull a0[6] = {qa0.x, qa0.y, qa1.x, qa1.y, qa2.x, qa2.y};
            ull b0[6] = {qb0.x, qb0.y, qb1.x, qb1.y, qb2.x, qb2.y};
            ull c0[6] = {qc0.x, qc0.y, qc1.x, qc1.y, qc2.x, qc2.y};
            ull d0[6] = {qd0.x, qd0.y, qd1.x, qd1.y, qd2.x, qd2.y};
            const float* wbase = &sm[OFF_W2T + k * 96];
#pragma unroll
            for (int o = 0; o < 12; o++) {
                const int p0 = (o < 8) ? ((o < 4) ? 0 : 2) : 0;
                const int p1 = (o < 4) ? 2 : 4;
                const ulonglong2* wp = (const ulonglong2*)(wbase + o * 8);
                ulonglong2 wA = wp[0], wB = wp[1];
                fma2(ac[o*4+0], a0[p0], wA.x); fma2(ac[o*4+0], a0[p0+1], wA.y);
                fma2(ac[o*4+0], a0[p1], wB.x); fma2(ac[o*4+0], a0[p1+1], wB.y);
                fma2(ac[o*4+1], b0[p0], wA.x); fma2(ac[o*4+1], b0[p0+1], wA.y);
                fma2(ac[o*4+1], b0[p1], wB.x); fma2(ac[o*4+1], b0[p1+1], wB.y);
                fma2(ac[o*4+2], c0[p0], wA.x); fma2(ac[o*4+2], c0[p0+1], wA.y);
                fma2(ac[o*4+2], c0[p1], wB.x); fma2(ac[o*4+2], c0[p1+1], wB.y);
                fma2(ac[o*4+3], d0[p0], wA.x); fma2(ac[o*4+3], d0[p0+1], wA.y);
                fma2(ac[o*4+3], d0[p1], wB.x); fma2(ac[o*4+3], d0[p1+1], wB.y);
            }
        }
        // cross-half reduce + bias + relu (keep in regs)
#pragma unroll
        for (int o = 0; o < 12; o++) {
            float bias = sm[OFF_H2B + o * 16 + pos];
#pragma unroll
            for (int q = 0; q < 4; q++) {
                float lo, hi;
                unpk2(ac[o * 4 + q], lo, hi);
                float r = lo + hi;
                r += __shfl_xor_sync(0xffffffffu, r, 16);
                float v = r + bias;
                vv[o * 4 + q] = v > 0.0f ? v : 0.0f;
            }
        }
    }
    __syncthreads();                                // C1 now dead

    // store o2 (overlay C1 region): o2[(o*16+pos)*49 + (w + q*12)]
    {
        int w = t >> 5, lane = t & 31;
        int khalf = lane >> 4, pos = lane & 15;
        if (khalf == 0) {
            float* o2 = &sm[OFF_O2];
#pragma unroll
            for (int o = 0; o < 12; o++) {
                int kk = (o * 16 + pos) * O2STR;
#pragma unroll
                for (int q = 0; q < 4; q++)
                    o2[kk + w + q * 12] = vv[o * 4 + q];
            }
        }
    }
    __syncthreads();

    // -------- Phase D: fc1 192->30 + relu (4 samples x 2 h / thread) ---------
    if (t < 180) {
        int h2 = t / 12, sp = t - h2 * 12;          // h2 0..14, samples sp+q*12
        int h0 = 2 * h2, h1 = h0 + 1;
        const float* o2 = &sm[OFF_O2];
        const ulonglong2* wp0 = (const ulonglong2*)&sm[OFF_W3T + h0 * 192];
        const ulonglong2* wp1 = (const ulonglong2*)&sm[OFF_W3T + h1 * 192];
        ull s0[4] = {0, 0, 0, 0};
        ull s1[4] = {0, 0, 0, 0};
#pragma unroll 4
        for (int k4 = 0; k4 < 48; k4++) {
            ulonglong2 wa = wp0[k4], wb = wp1[k4];
            int k = 4 * k4;
#pragma unroll
            for (int q = 0; q < 4; q++) {
                int s = sp + q * 12;
                float a0 = o2[(k+0)*O2STR + s], a1 = o2[(k+1)*O2STR + s];
                float a2 = o2[(k+2)*O2STR + s], a3 = o2[(k+3)*O2STR + s];
                ull v01 = pk2(a0, a1), v23 = pk2(a2, a3);
                fma2(s0[q], v01, wa.x); fma2(s0[q], v23, wa.y);
                fma2(s1[q], v01, wb.x); fma2(s1[q], v23, wb.y);
            }
        }
        float bb0 = sm[OFF_H3B + h0], bb1 = sm[OFF_H3B + h1];
#pragma unroll
        for (int q = 0; q < 4; q++) {
            int s = sp + q * 12;
            float lo, hi;
            unpk2(s0[q], lo, hi); float v0 = lo + hi + bb0;
            unpk2(s1[q], lo, hi); float v1 = lo + hi + bb1;
            sm[OFF_HID + s * 32 + h0] = v0 > 0.0f ? v0 : 0.0f;
            sm[OFF_HID + s * 32 + h1] = v1 > 0.0f ? v1 : 0.0f;
        }
    }
    __syncthreads();

    // ---------------- Phase E: fc2 30->10 (2 samples/thread) -----------------
    if (t < 240) {
        int s = t / 10, o = t - s * 10;             // s 0..23, samples s, s+24
        float sum0 = sm[OFF_OUTB + o], sum1 = sum0;
        const float* h0 = &sm[OFF_HID + s * 32];
        const float* h1 = &sm[OFF_HID + (s + 24) * 32];
#pragma unroll
        for (int h = 0; h < 30; h++) {
            float w = sm[OFF_OUTW + h * 10 + o];
            sum0 += h0[h] * w;
            sum1 += h1[h] * w;
        }
        long g0 = base_s + s, g1 = base_s + s + 24;
        if (g0 < nsamp) out[g0 * 10 + o] = sum0;
        if (g1 < nsamp) out[g1 * 10 + o] = sum1;
    }
}

extern "C" void kernel_launch(void* const* d_in, const int* in_sizes, int n_in,
                              void* d_out, int out_size)
{
    const float* x  = (const float*)d_in[0];
    const float* w1 = (const float*)d_in[1];
    const float* b1 = (const float*)d_in[2];
    const float* w2 = (const float*)d_in[3];
    const float* b2 = (const float*)d_in[4];
    const float* w3 = (const float*)d_in[5];
    const float* b3 = (const float*)d_in[6];
    const float* wo = (const float*)d_in[7];
    const float* bo = (const float*)d_in[8];
    float* out = (float*)d_out;

    int nsamp = in_sizes[0] / 256;                       // 131072
    int grid  = (nsamp + SAMPLES - 1) / SAMPLES;         // 2731
    size_t smem = SMEM_FLOATS * sizeof(float);           // 225824 B

    cudaFuncSetAttribute(modernnet_fused_kernel,
                         cudaFuncAttributeMaxDynamicSharedMemorySize, (int)smem);
    modernnet_fused_kernel<<<grid, THREADS, smem>>>(x, w1, b1, w2, b2, w3, b3,
                                                    wo, bo, out, nsamp);
}